// round 1
// baseline (speedup 1.0000x reference)
#include <cuda_runtime.h>
#include <cstdint>

// Problem shape (fixed by the dataset): B=4, S=2048, D=4096
#define DDIM   4096
#define M_ROWS 8192          // B*S token rows
#define N_ROWS 4096          // output features
#define KI     (DDIM / 4)    // K in packed-int units (4 int8 per int)

// ---------------- scratch (allocation-free: __device__ globals) ----------------
__device__ int   g_qx[(size_t)M_ROWS * KI];   // quantized x  (packed int8x4), 33.5MB
__device__ int   g_qw[(size_t)N_ROWS * KI];   // quantized w  (packed int8x4), 16.8MB
__device__ float g_sa[M_ROWS];                // ax/127 per token row
__device__ float g_sw[N_ROWS];                // aw/127 per output row

// ---------------- row-wise absmax int8 quantization ----------------
// One block per row. MUL=true: t = src*scales (x path). MUL=false: t = src/scales (w path).
template <bool MUL>
__global__ __launch_bounds__(256) void quant_rows_kernel(
    const float* __restrict__ src, const float* __restrict__ scales,
    int* __restrict__ q, float* __restrict__ qscale)
{
    const int row = blockIdx.x;
    const int tid = threadIdx.x;
    const float4* src4 = reinterpret_cast<const float4*>(src + (size_t)row * DDIM);
    const float4* scl4 = reinterpret_cast<const float4*>(scales);

    // 4096 floats / 256 threads = 16 per thread, as 4 float4 (coalesced, stride 256)
    float v[16];
    float m = 0.f;
    #pragma unroll
    for (int i = 0; i < 4; i++) {
        int g = i * 256 + tid;                 // float4 index 0..1023
        float4 x = src4[g];
        float4 s = scl4[g];
        float t0, t1, t2, t3;
        if (MUL) { t0 = x.x * s.x; t1 = x.y * s.y; t2 = x.z * s.z; t3 = x.w * s.w; }
        else     { t0 = x.x / s.x; t1 = x.y / s.y; t2 = x.z / s.z; t3 = x.w / s.w; }
        v[i*4+0] = t0; v[i*4+1] = t1; v[i*4+2] = t2; v[i*4+3] = t3;
        m = fmaxf(m, fmaxf(fmaxf(fabsf(t0), fabsf(t1)), fmaxf(fabsf(t2), fabsf(t3))));
    }

    // block max reduction
    __shared__ float red[8];
    #pragma unroll
    for (int o = 16; o > 0; o >>= 1)
        m = fmaxf(m, __shfl_xor_sync(0xffffffffu, m, o));
    if ((tid & 31) == 0) red[tid >> 5] = m;
    __syncthreads();
    if (tid < 32) {
        float t = (tid < 8) ? red[tid] : 0.f;
        #pragma unroll
        for (int o = 4; o > 0; o >>= 1)
            t = fmaxf(t, __shfl_xor_sync(0xffffffffu, t, o));
        if (tid == 0) red[0] = fmaxf(t, 1e-8f);
    }
    __syncthreads();
    const float absmax = red[0];
    const float qs = 127.f / absmax;

    // quantize + pack 4 int8 into one int (little-endian: elem k*4+0 -> byte0, matches dp4a)
    int* qrow = q + (size_t)row * KI;
    #pragma unroll
    for (int i = 0; i < 4; i++) {
        int g = i * 256 + tid;                 // packed-int index 0..1023
        int packed = 0;
        #pragma unroll
        for (int j = 0; j < 4; j++) {
            float t = rintf(v[i*4+j] * qs);
            t = fminf(fmaxf(t, -127.f), 127.f);
            packed |= ((int)t & 0xff) << (8 * j);
        }
        qrow[g] = packed;
    }
    if (tid == 0) qscale[row] = absmax * (1.f / 127.f);
}

// ---------------- int8 NT GEMM via dp4a, 128x128 tile, 256 threads ----------------
#define BM  128
#define BN  128
#define BKI 16      // K-chunk in packed ints (= 64 int8)
#define PAD 4

__global__ __launch_bounds__(256) void gemm_dp4a_kernel(
    const float* __restrict__ bias, const float* __restrict__ scales,
    float* __restrict__ out)
{
    __shared__ int As[BKI][BM + PAD];   // [ki][m]  (transposed so frag loads are contiguous)
    __shared__ int Bs[BKI][BN + PAD];   // [ki][n]

    const int tid = threadIdx.x;
    const int tx  = tid & 15;           // n direction (16)
    const int ty  = tid >> 4;           // m direction (16)
    const int m0  = blockIdx.y * BM;
    const int n0  = blockIdx.x * BN;

    int acc[8][8];
    #pragma unroll
    for (int i = 0; i < 8; i++)
        #pragma unroll
        for (int j = 0; j < 8; j++) acc[i][j] = 0;

    for (int kk = 0; kk < KI; kk += BKI) {
        // Load tiles: 128 rows x 16 ints each = 512 int4 loads per matrix; 2 per thread
        #pragma unroll
        for (int i = 0; i < 2; i++) {
            int idx = tid * 2 + i;        // 0..511
            int r   = idx >> 2;           // row within tile 0..127
            int kg  = idx & 3;            // which int4 within the 16-int K-chunk
            int4 a = *reinterpret_cast<const int4*>(&g_qx[(size_t)(m0 + r) * KI + kk + kg * 4]);
            As[kg*4+0][r] = a.x; As[kg*4+1][r] = a.y; As[kg*4+2][r] = a.z; As[kg*4+3][r] = a.w;
            int4 b = *reinterpret_cast<const int4*>(&g_qw[(size_t)(n0 + r) * KI + kk + kg * 4]);
            Bs[kg*4+0][r] = b.x; Bs[kg*4+1][r] = b.y; Bs[kg*4+2][r] = b.z; Bs[kg*4+3][r] = b.w;
        }
        __syncthreads();

        #pragma unroll
        for (int ki = 0; ki < BKI; ki++) {
            int a[8], b[8];
            *reinterpret_cast<int4*>(&a[0]) = *reinterpret_cast<const int4*>(&As[ki][ty * 8]);
            *reinterpret_cast<int4*>(&a[4]) = *reinterpret_cast<const int4*>(&As[ki][ty * 8 + 4]);
            *reinterpret_cast<int4*>(&b[0]) = *reinterpret_cast<const int4*>(&Bs[ki][tx * 8]);
            *reinterpret_cast<int4*>(&b[4]) = *reinterpret_cast<const int4*>(&Bs[ki][tx * 8 + 4]);
            #pragma unroll
            for (int i = 0; i < 8; i++)
                #pragma unroll
                for (int j = 0; j < 8; j++)
                    acc[i][j] = __dp4a(a[i], b[j], acc[i][j]);
        }
        __syncthreads();
    }

    // Epilogue: out = acc * sa[m] * sw[n] + bias[n]/scales[n]
    float fw[8], fb[8];
    #pragma unroll
    for (int j = 0; j < 8; j++) {
        int n = n0 + tx * 8 + j;
        fw[j] = g_sw[n];
        fb[j] = bias[n] / scales[n];
    }
    #pragma unroll
    for (int i = 0; i < 8; i++) {
        int m = m0 + ty * 8 + i;
        float fa = g_sa[m];
        float4* orow = reinterpret_cast<float4*>(out + (size_t)m * N_ROWS + n0 + tx * 8);
        float4 o0, o1;
        o0.x = acc[i][0] * fa * fw[0] + fb[0];
        o0.y = acc[i][1] * fa * fw[1] + fb[1];
        o0.z = acc[i][2] * fa * fw[2] + fb[2];
        o0.w = acc[i][3] * fa * fw[3] + fb[3];
        o1.x = acc[i][4] * fa * fw[4] + fb[4];
        o1.y = acc[i][5] * fa * fw[5] + fb[5];
        o1.z = acc[i][6] * fa * fw[6] + fb[6];
        o1.w = acc[i][7] * fa * fw[7] + fb[7];
        orow[0] = o0;
        orow[1] = o1;
    }
}

// ---------------- launch ----------------
extern "C" void kernel_launch(void* const* d_in, const int* in_sizes, int n_in,
                              void* d_out, int out_size)
{
    const float* x      = (const float*)d_in[0];   // [4,2048,4096]
    const float* weight = (const float*)d_in[1];   // [4096,4096]
    const float* bias   = (const float*)d_in[2];   // [4096]
    const float* scales = (const float*)d_in[3];   // [4096]
    float* out = (float*)d_out;                    // [4,2048,4096]

    int* qx; int* qw; float* sa; float* sw;
    cudaGetSymbolAddress((void**)&qx, g_qx);
    cudaGetSymbolAddress((void**)&qw, g_qw);
    cudaGetSymbolAddress((void**)&sa, g_sa);
    cudaGetSymbolAddress((void**)&sw, g_sw);

    quant_rows_kernel<true ><<<M_ROWS, 256>>>(x,      scales, qx, sa);
    quant_rows_kernel<false><<<N_ROWS, 256>>>(weight, scales, qw, sw);

    dim3 grid(N_ROWS / BN, M_ROWS / BM);   // (32, 64)
    gemm_dp4a_kernel<<<grid, 256>>>(bias, scales, out);
}

// round 3
// speedup vs baseline: 1.0706x; 1.0706x over previous
#include <cuda_runtime.h>
#include <cstdint>

// Problem shape (fixed by the dataset): B=4, S=2048, D=4096
#define DDIM   4096
#define M_ROWS 8192          // B*S token rows
#define N_ROWS 4096          // output features
#define KI     (DDIM / 4)    // K in packed-int units (4 int8 per int)

// ---------------- scratch (allocation-free: __device__ globals) ----------------
__device__ int   g_qx[(size_t)M_ROWS * KI];   // quantized x  (packed int8x4)
__device__ int   g_qw[(size_t)N_ROWS * KI];   // quantized w  (packed int8x4)
__device__ float g_sa[M_ROWS];                // ax/127 per token row
__device__ float g_sw[N_ROWS];                // aw/127 per output row

// ---------------- row-wise absmax int8 quantization ----------------
template <bool MUL>
__global__ __launch_bounds__(256) void quant_rows_kernel(
    const float* __restrict__ src, const float* __restrict__ scales,
    int* __restrict__ q, float* __restrict__ qscale)
{
    const int row = blockIdx.x;
    const int tid = threadIdx.x;
    const float4* src4 = reinterpret_cast<const float4*>(src + (size_t)row * DDIM);
    const float4* scl4 = reinterpret_cast<const float4*>(scales);

    float v[16];
    float m = 0.f;
    #pragma unroll
    for (int i = 0; i < 4; i++) {
        int g = i * 256 + tid;
        float4 x = src4[g];
        float4 s = scl4[g];
        float t0, t1, t2, t3;
        if (MUL) { t0 = x.x * s.x; t1 = x.y * s.y; t2 = x.z * s.z; t3 = x.w * s.w; }
        else     { t0 = x.x / s.x; t1 = x.y / s.y; t2 = x.z / s.z; t3 = x.w / s.w; }
        v[i*4+0] = t0; v[i*4+1] = t1; v[i*4+2] = t2; v[i*4+3] = t3;
        m = fmaxf(m, fmaxf(fmaxf(fabsf(t0), fabsf(t1)), fmaxf(fabsf(t2), fabsf(t3))));
    }

    __shared__ float red[8];
    #pragma unroll
    for (int o = 16; o > 0; o >>= 1)
        m = fmaxf(m, __shfl_xor_sync(0xffffffffu, m, o));
    if ((tid & 31) == 0) red[tid >> 5] = m;
    __syncthreads();
    if (tid < 32) {
        float t = (tid < 8) ? red[tid] : 0.f;
        #pragma unroll
        for (int o = 4; o > 0; o >>= 1)
            t = fmaxf(t, __shfl_xor_sync(0xffffffffu, t, o));
        if (tid == 0) red[0] = fmaxf(t, 1e-8f);
    }
    __syncthreads();
    const float absmax = red[0];
    const float qs = 127.f / absmax;

    int* qrow = q + (size_t)row * KI;
    #pragma unroll
    for (int i = 0; i < 4; i++) {
        int g = i * 256 + tid;
        int packed = 0;
        #pragma unroll
        for (int j = 0; j < 4; j++) {
            float t = rintf(v[i*4+j] * qs);
            t = fminf(fmaxf(t, -127.f), 127.f);
            packed |= ((int)t & 0xff) << (8 * j);
        }
        qrow[g] = packed;
    }
    if (tid == 0) qscale[row] = absmax * (1.f / 127.f);
}

// ---------------- int8 NT GEMM via mma.sync m16n8k32 (IMMA) ----------------
// Block tile 128x128, BK=64 int8 (16 ints). 8 warps (2x4), each warp 64x32.
#define BM  128
#define BN  128
#define BKI 16              // K-chunk in packed ints (= 64 int8)
#define SSTR 20             // smem row stride in ints (16 + 4 pad: conflict-free)

__device__ __forceinline__ void imma16832(int& c0, int& c1, int& c2, int& c3,
                                          int a0, int a1, int a2, int a3,
                                          int b0, int b1)
{
    asm volatile(
        "mma.sync.aligned.m16n8k32.row.col.s32.s8.s8.s32 "
        "{%0,%1,%2,%3}, {%4,%5,%6,%7}, {%8,%9}, {%0,%1,%2,%3};\n"
        : "+r"(c0), "+r"(c1), "+r"(c2), "+r"(c3)
        : "r"(a0), "r"(a1), "r"(a2), "r"(a3), "r"(b0), "r"(b1));
}

__global__ __launch_bounds__(256, 2) void gemm_imma_kernel(
    const float* __restrict__ bias, const float* __restrict__ scales,
    float* __restrict__ out)
{
    __shared__ int As[BM][SSTR];   // [m][ki within chunk]
    __shared__ int Bs[BN][SSTR];   // [n][ki within chunk]

    const int tid  = threadIdx.x;
    const int wid  = tid >> 5;
    const int lane = tid & 31;
    const int g    = lane >> 2;     // group id 0..7
    const int tig  = lane & 3;      // thread in group 0..3
    const int wm   = wid >> 2;      // 0..1  (m dir)
    const int wn   = wid & 3;       // 0..3  (n dir)
    const int m0   = blockIdx.y * BM;
    const int n0   = blockIdx.x * BN;

    int acc[4][4][4];               // [mt][nt][c0..c3]
    #pragma unroll
    for (int i = 0; i < 4; i++)
        #pragma unroll
        for (int j = 0; j < 4; j++)
            #pragma unroll
            for (int c = 0; c < 4; c++) acc[i][j][c] = 0;

    for (int kk = 0; kk < KI; kk += BKI) {
        // Stage tiles: each matrix 128 rows x 16 ints = 512 int4; 2 per thread
        #pragma unroll
        for (int i = 0; i < 2; i++) {
            int idx = tid * 2 + i;          // 0..511
            int r   = idx >> 2;             // tile row
            int kg  = idx & 3;              // int4 within the 16-int chunk
            int4 a = *reinterpret_cast<const int4*>(&g_qx[(size_t)(m0 + r) * KI + kk + kg * 4]);
            As[r][kg*4+0] = a.x; As[r][kg*4+1] = a.y; As[r][kg*4+2] = a.z; As[r][kg*4+3] = a.w;
            int4 b = *reinterpret_cast<const int4*>(&g_qw[(size_t)(n0 + r) * KI + kk + kg * 4]);
            Bs[r][kg*4+0] = b.x; Bs[r][kg*4+1] = b.y; Bs[r][kg*4+2] = b.z; Bs[r][kg*4+3] = b.w;
        }
        __syncthreads();

        #pragma unroll
        for (int ks = 0; ks < 2; ks++) {    // two k32 steps per 64-byte chunk
            int a[4][4], b[4][2];
            #pragma unroll
            for (int mt = 0; mt < 4; mt++) {
                int r = wm * 64 + mt * 16 + g;
                // PTX m16n8k32.s8 A layout: a0=(g,k-lo) a1=(g+8,k-lo) a2=(g,k-hi) a3=(g+8,k-hi)
                a[mt][0] = As[r    ][ks*8 + tig    ];
                a[mt][1] = As[r + 8][ks*8 + tig    ];
                a[mt][2] = As[r    ][ks*8 + tig + 4];
                a[mt][3] = As[r + 8][ks*8 + tig + 4];
            }
            #pragma unroll
            for (int nt = 0; nt < 4; nt++) {
                int r = wn * 32 + nt * 8 + g;
                b[nt][0] = Bs[r][ks*8 + tig    ];
                b[nt][1] = Bs[r][ks*8 + tig + 4];
            }
            #pragma unroll
            for (int mt = 0; mt < 4; mt++)
                #pragma unroll
                for (int nt = 0; nt < 4; nt++)
                    imma16832(acc[mt][nt][0], acc[mt][nt][1], acc[mt][nt][2], acc[mt][nt][3],
                              a[mt][0], a[mt][1], a[mt][2], a[mt][3],
                              b[nt][0], b[nt][1]);
        }
        __syncthreads();
    }

    // Epilogue: out[m][n] = acc * sa[m]*sw[n] + bias[n]/scales[n]
    // C fragment: c0 (g, 2tig), c1 (g, 2tig+1), c2 (g+8, 2tig), c3 (g+8, 2tig+1)
    float fw[4][2], fb[4][2];
    #pragma unroll
    for (int nt = 0; nt < 4; nt++) {
        int n = n0 + wn * 32 + nt * 8 + 2 * tig;
        fw[nt][0] = g_sw[n];
        fw[nt][1] = g_sw[n + 1];
        fb[nt][0] = __ldg(&bias[n])     / __ldg(&scales[n]);
        fb[nt][1] = __ldg(&bias[n + 1]) / __ldg(&scales[n + 1]);
    }
    #pragma unroll
    for (int mt = 0; mt < 4; mt++) {
        int mA = m0 + wm * 64 + mt * 16 + g;
        float saA = g_sa[mA];
        float saB = g_sa[mA + 8];
        #pragma unroll
        for (int nt = 0; nt < 4; nt++) {
            int n = n0 + wn * 32 + nt * 8 + 2 * tig;
            float2 o0, o1;
            o0.x = acc[mt][nt][0] * saA * fw[nt][0] + fb[nt][0];
            o0.y = acc[mt][nt][1] * saA * fw[nt][1] + fb[nt][1];
            o1.x = acc[mt][nt][2] * saB * fw[nt][0] + fb[nt][0];
            o1.y = acc[mt][nt][3] * saB * fw[nt][1] + fb[nt][1];
            *reinterpret_cast<float2*>(out + (size_t)mA       * N_ROWS + n) = o0;
            *reinterpret_cast<float2*>(out + (size_t)(mA + 8) * N_ROWS + n) = o1;
        }
    }
}

// ---------------- launch ----------------
extern "C" void kernel_launch(void* const* d_in, const int* in_sizes, int n_in,
                              void* d_out, int out_size)
{
    const float* x      = (const float*)d_in[0];   // [4,2048,4096]
    const float* weight = (const float*)d_in[1];   // [4096,4096]
    const float* bias   = (const float*)d_in[2];   // [4096]
    const float* scales = (const float*)d_in[3];   // [4096]
    float* out = (float*)d_out;                    // [4,2048,4096]

    int* qx; int* qw; float* sa; float* sw;
    cudaGetSymbolAddress((void**)&qx, g_qx);
    cudaGetSymbolAddress((void**)&qw, g_qw);
    cudaGetSymbolAddress((void**)&sa, g_sa);
    cudaGetSymbolAddress((void**)&sw, g_sw);

    quant_rows_kernel<true ><<<M_ROWS, 256>>>(x,      scales, qx, sa);
    quant_rows_kernel<false><<<N_ROWS, 256>>>(weight, scales, qw, sw);

    dim3 grid(N_ROWS / BN, M_ROWS / BM);   // (32, 64)
    gemm_imma_kernel<<<grid, 256>>>(bias, scales, out);
}